// round 13
// baseline (speedup 1.0000x reference)
#include <cuda_runtime.h>
#include <cstdint>

typedef unsigned long long u64;

#define N_TOKENS  131072
#define NUM_CODES 1024
#define CODE_DIM  64
#define DECAY     0.99f
#define OMD       0.01f
#define EPS       1e-5f

#define OUT_Q     0
#define OUT_IDX   (N_TOKENS * CODE_DIM)
#define OUT_LOSS  (OUT_IDX + N_TOKENS)
#define OUT_CB    (OUT_LOSS + 1)
#define OUT_CS    (OUT_CB + NUM_CODES * CODE_DIM)
#define OUT_EMA   (OUT_CS + NUM_CODES)

#define NCHUNK     32                 // 32 chunks x 32 codes
#define CROW       272                // code row: 32 dup codes interleaved (16B gap mid-row)
#define CBUF       (64 * CROW)        // 17408 B per chunk buffer
#define CBUF_U64   (CBUF / 8)         // 2176

// smem layout (bytes)
#define SM_ZS     0                   // 64 d-rows x 128 tokens x 4B = 32768
#define SM_C0     32768
#define SM_C1     (SM_C0 + CBUF)      // 50176
#define SM_CNS    (SM_C1 + CBUF)      // 67584 (+4096)
#define SM_SIDX   71680               // 128 int
#define SM_SBEST  72192               // 128 float
#define SMEM_BYTES 72704

// ---------------- device scratch ----------------
__device__ __align__(16) u64 g_cbp[NCHUNK * CBUF_U64];  // smem-image of code tiles
__device__ float g_dw[NUM_CODES * CODE_DIM];
__device__ float g_counts[NUM_CODES];
__device__ float g_cnorm[NUM_CODES];
__device__ float g_inv[NUM_CODES];
__device__ float g_loss;

// ---------------- helpers ----------------
__device__ __forceinline__ uint32_t smem_u32(const void* p) {
    uint32_t a;
    asm("{ .reg .u64 t; cvta.to.shared.u64 t, %1; cvt.u32.u64 %0, t; }" : "=r"(a) : "l"(p));
    return a;
}
__device__ __forceinline__ u64 pk2(float x, float y) {
    u64 r; asm("mov.b64 %0, {%1, %2};" : "=l"(r) : "f"(x), "f"(y)); return r;
}
__device__ __forceinline__ void upk2(u64 v, float& x, float& y) {
    asm("mov.b64 {%0, %1}, %2;" : "=f"(x), "=f"(y) : "l"(v));
}
__device__ __forceinline__ u64 fma2(u64 a, u64 b, u64 c) {
    u64 r; asm("fma.rn.f32x2 %0, %1, %2, %3;" : "=l"(r) : "l"(a), "l"(b), "l"(c)); return r;
}
__device__ __forceinline__ void cpa16(uint32_t dst, const void* src) {
    asm volatile("cp.async.cg.shared.global [%0], [%1], 16;" :: "r"(dst), "l"(src));
}
#define CP_COMMIT() asm volatile("cp.async.commit_group;" ::: "memory")
#define CP_WAIT1()  asm volatile("cp.async.wait_group 1;" ::: "memory")
#define CP_WAIT0()  asm volatile("cp.async.wait_group 0;" ::: "memory")

// ---------------- prep kernels (assign at launch position 3 for ncu) ----------------
__global__ void prep_zero_a_kernel() {
    int i = blockIdx.x * 256 + threadIdx.x;   // 8192 -> lower half of g_dw
    ((float4*)g_dw)[i] = make_float4(0.f, 0.f, 0.f, 0.f);
    if (i < NUM_CODES) g_counts[i] = 0.0f;
}

// g_cbp[c][d][slot(k)] = (cb[c*32+k][d], cb[c*32+k][d]) ; slot(k) = k + (k>>4)*2 (u64 units)
__global__ void prep_cb_kernel(const float* __restrict__ cb) {
    int i = blockIdx.x * 256 + threadIdx.x;   // 65536 threads: [c(32)][d(64)][k(32)]
    int c = i >> 11, r = i & 2047;
    int d = r >> 5, k = r & 31;
    int kg = c * 32 + k;
    float v = cb[(size_t)kg * 64 + d];
    g_cbp[c * CBUF_U64 + d * 34 + k + ((k >> 4) << 1)] = pk2(v, v);
    if (i < NUM_CODES) {
        float s = 0.0f;
        const float4* cr = (const float4*)(cb + (size_t)i * 64);
#pragma unroll
        for (int j = 0; j < 16; j++) {
            float4 w = cr[j];
            s += w.x * w.x + w.y * w.y + w.z * w.z + w.w * w.w;
        }
        g_cnorm[i] = s;
    }
}

__global__ void prep_zero_b_kernel() {
    int i = blockIdx.x * 256 + threadIdx.x;   // 8192 -> upper half of g_dw
    ((float4*)g_dw)[8192 + i] = make_float4(0.f, 0.f, 0.f, 0.f);
    if (i == 0) g_loss = 0.0f;
}

// ---------------- assign: token-packed f32x2 GEMM ----------------
// 128 threads, 128 tokens/CTA, 1024 CTAs. cg = tid&7 (4 codes), tgrp = tid>>3 (8 tokens).
// acc[q][p] = (dot(t_{2p},code q), dot(t_{2p+1},code q)). 32 chunks of 32 codes.
__global__ void __launch_bounds__(128, 3)
assign_kernel(const float4* __restrict__ z4, const float4* __restrict__ cb4,
              float* __restrict__ out) {
    extern __shared__ __align__(16) char smem[];
    float* cns   = (float*)(smem + SM_CNS);
    int*   sidx  = (int*)(smem + SM_SIDX);
    float* sbest = (float*)(smem + SM_SBEST);

    const int tid  = threadIdx.x;
    const int cg   = tid & 7;
    const int tgrp = tid >> 3;           // owns tokens tgrp*8..tgrp*8+7
    const int base = blockIdx.x * 128;
    const uint32_t sbase = smem_u32(smem);

    // ---- stage z: thread owns token tid; zs[d][t] plain f32 (512B rows)
    {
        const float4* zsrc = z4 + (size_t)(base + tid) * 16;
#pragma unroll
        for (int j = 0; j < 16; j++) {
            float4 v = zsrc[j];
            *(float*)(smem + SM_ZS + (4 * j + 0) * 512 + tid * 4) = v.x;
            *(float*)(smem + SM_ZS + (4 * j + 1) * 512 + tid * 4) = v.y;
            *(float*)(smem + SM_ZS + (4 * j + 2) * 512 + tid * 4) = v.z;
            *(float*)(smem + SM_ZS + (4 * j + 3) * 512 + tid * 4) = v.w;
        }
    }
    // ---- resident code norms
#pragma unroll
    for (int i = 0; i < 8; i++) cns[tid + i * 128] = g_cnorm[tid + i * 128];

    // ---- cp.async prologue: chunk 0 -> buf0 (linear 17408B = 1088 x 16B)
    {
        const char* src = (const char*)g_cbp;
#pragma unroll
        for (int i = 0; i < 9; i++) {
            int l = tid + i * 128;
            if (l < 1088) cpa16(sbase + SM_C0 + l * 16, src + (size_t)l * 16);
        }
        CP_COMMIT();
    }

    float best[8];
    int   bidx[8];
#pragma unroll
    for (int t = 0; t < 8; t++) { best[t] = 3.0e38f; bidx[t] = 0; }
    const u64 NEG2 = pk2(-2.0f, -2.0f);

    for (int c = 0; c < NCHUNK; c++) {
        __syncthreads();   // prior compute done with the buffer we're about to fill
        if (c < NCHUNK - 1) {
            const char* src = (const char*)(g_cbp + (size_t)(c + 1) * CBUF_U64);
            uint32_t boff = ((c + 1) & 1) ? SM_C1 : SM_C0;
#pragma unroll
            for (int i = 0; i < 9; i++) {
                int l = tid + i * 128;
                if (l < 1088) cpa16(sbase + boff + l * 16, src + (size_t)l * 16);
            }
            CP_COMMIT();
            CP_WAIT1();    // chunk c's copy complete
        } else {
            CP_WAIT0();
        }
        __syncthreads();   // chunk c visible

        const char* cbuf = smem + ((c & 1) ? SM_C1 : SM_C0);
        const uint32_t coff = cg * 32 + ((cg >> 2) << 4);   // conflict-free slot base

        u64 acc[16];
#pragma unroll
        for (int i = 0; i < 16; i++) acc[i] = 0ull;

#pragma unroll 8
        for (int d = 0; d < 64; d++) {
            // z: 4 token-pairs, natural float2 packing (2 LDS.128, broadcast x8)
            const char* zr = smem + SM_ZS + d * 512 + tgrp * 32;
            ulonglong2 za = *(const ulonglong2*)zr;          // pairs 0,1
            ulonglong2 zb = *(const ulonglong2*)(zr + 16);   // pairs 2,3
            // codes: 4 dup codes (2 LDS.128, conflict-free)
            const char* cr = cbuf + d * CROW + coff;
            ulonglong2 ca  = *(const ulonglong2*)cr;         // codes 0,1
            ulonglong2 cb2 = *(const ulonglong2*)(cr + 16);  // codes 2,3
            u64 zp0 = za.x, zp1 = za.y, zp2 = zb.x, zp3 = zb.y;
            u64 cc0 = ca.x, cc1 = ca.y, cc2 = cb2.x, cc3 = cb2.y;
            acc[0]  = fma2(zp0, cc0, acc[0]);
            acc[1]  = fma2(zp1, cc0, acc[1]);
            acc[2]  = fma2(zp2, cc0, acc[2]);
            acc[3]  = fma2(zp3, cc0, acc[3]);
            acc[4]  = fma2(zp0, cc1, acc[4]);
            acc[5]  = fma2(zp1, cc1, acc[5]);
            acc[6]  = fma2(zp2, cc1, acc[6]);
            acc[7]  = fma2(zp3, cc1, acc[7]);
            acc[8]  = fma2(zp0, cc2, acc[8]);
            acc[9]  = fma2(zp1, cc2, acc[9]);
            acc[10] = fma2(zp2, cc2, acc[10]);
            acc[11] = fma2(zp3, cc2, acc[11]);
            acc[12] = fma2(zp0, cc3, acc[12]);
            acc[13] = fma2(zp1, cc3, acc[13]);
            acc[14] = fma2(zp2, cc3, acc[14]);
            acc[15] = fma2(zp3, cc3, acc[15]);
        }

        // ---- epilogue: per code q, score pair per token pair; running argmin
        const int kb = c * 32;
#pragma unroll
        for (int q = 0; q < 4; q++) {
            int k = kb + cg * 4 + q;
            float cn = cns[k];
            u64 cnp = pk2(cn, cn);
#pragma unroll
            for (int p = 0; p < 4; p++) {
                u64 sp = fma2(acc[q * 4 + p], NEG2, cnp);
                float s0, s1;
                upk2(sp, s0, s1);
                if (s0 < best[2 * p])     { best[2 * p] = s0;     bidx[2 * p] = k; }
                if (s1 < best[2 * p + 1]) { best[2 * p + 1] = s1; bidx[2 * p + 1] = k; }
            }
        }
    }

    // ---- cross-lane argmin over 8 cg lanes (lane bits 0..2), tie-break lowest index
#pragma unroll
    for (int t = 0; t < 8; t++) {
        float v = best[t];
        int   i = bidx[t];
#pragma unroll
        for (int off = 1; off <= 4; off <<= 1) {
            float ov = __shfl_xor_sync(0xffffffffu, v, off);
            int   oi = __shfl_xor_sync(0xffffffffu, i, off);
            if (ov < v || (ov == v && oi < i)) { v = ov; i = oi; }
        }
        if (cg == 0) { sidx[tgrp * 8 + t] = i; sbest[tgrp * 8 + t] = v; }
    }
    __syncthreads();

    // ---- scatter: thread owns token tid (z from smem, conflict-free)
    {
        int idx = sidx[tid];
        int tok = base + tid;
        out[OUT_IDX + tok] = (float)idx;
        atomicAdd(&g_counts[idx], 1.0f);
        float zn = 0.0f;
        float* dwp = &g_dw[idx * 64];
#pragma unroll 8
        for (int d = 0; d < 64; d++) {
            float zv = *(const float*)(smem + SM_ZS + d * 512 + tid * 4);
            zn += zv * zv;
            atomicAdd(&dwp[d], zv);
        }
        float lp = zn + sbest[tid];   // exact d2min
#pragma unroll
        for (int off = 16; off > 0; off >>= 1)
            lp += __shfl_down_sync(0xffffffffu, lp, off);
        if ((tid & 31) == 0) atomicAdd(&g_loss, lp);
    }

    // ---- quantized: cooperative coalesced gather
    float4* outq = (float4*)out;   // OUT_Q == 0
#pragma unroll
    for (int i = 0; i < 16; i++) {
        int l = tid + i * 128;
        int t = l >> 4, j = l & 15;
        outq[(size_t)(base + t) * 16 + j] = cb4[(size_t)sidx[t] * 16 + j];
    }
}

// ---------------- finalize A: per-code stats + loss ----------------
__global__ void finalize_a_kernel(const float* __restrict__ cs_in,
                                  float* __restrict__ out) {
    __shared__ float s[1024];
    int k = threadIdx.x;
    float ncs = DECAY * cs_in[k] + OMD * g_counts[k];
    s[k] = ncs;
    __syncthreads();
    for (int st = 512; st > 0; st >>= 1) {
        if (k < st) s[k] += s[k + st];
        __syncthreads();
    }
    float n   = s[0];
    float csk = (ncs + EPS) / (n + NUM_CODES * EPS) * n;
    out[OUT_CS + k] = ncs;
    g_inv[k] = 1.0f / csk;
    if (k == 0) out[OUT_LOSS] = g_loss * (1.0f / (float)(N_TOKENS * CODE_DIM));
}

// ---------------- finalize B: parallel EMA + codebook update ----------------
__global__ void finalize_b_kernel(const float* __restrict__ ema_in,
                                  float* __restrict__ out) {
    int i = blockIdx.x * 256 + threadIdx.x;   // 65536 threads
    float e = DECAY * ema_in[i] + OMD * g_dw[i];
    out[OUT_EMA + i] = e;
    out[OUT_CB + i]  = e * g_inv[i >> 6];
}

extern "C" void kernel_launch(void* const* d_in, const int* in_sizes, int n_in,
                              void* d_out, int out_size) {
    const float* z   = (const float*)d_in[0];
    const float* cb  = (const float*)d_in[1];
    const float* cs  = (const float*)d_in[2];
    const float* ema = (const float*)d_in[3];
    float* out = (float*)d_out;

    static int smem_set = 0;
    if (!smem_set) {
        cudaFuncSetAttribute(assign_kernel,
                             cudaFuncAttributeMaxDynamicSharedMemorySize, SMEM_BYTES);
        smem_set = 1;
    }

    prep_zero_a_kernel<<<32, 256>>>();                                   // pos 0
    prep_cb_kernel<<<256, 256>>>(cb);                                    // pos 1
    prep_zero_b_kernel<<<32, 256>>>();                                   // pos 2
    assign_kernel<<<1024, 128, SMEM_BYTES>>>((const float4*)z,           // pos 3
                                             (const float4*)cb, out);
    finalize_a_kernel<<<1, 1024>>>(cs, out);                             // pos 4
    finalize_b_kernel<<<256, 256>>>(ema, out);                           // pos 5
}

// round 14
// speedup vs baseline: 1.0501x; 1.0501x over previous
#include <cuda_runtime.h>
#include <cstdint>

typedef unsigned long long u64;

#define N_TOKENS  131072
#define NUM_CODES 1024
#define CODE_DIM  64
#define DECAY     0.99f
#define OMD       0.01f
#define EPS       1e-5f

#define OUT_Q     0
#define OUT_IDX   (N_TOKENS * CODE_DIM)
#define OUT_LOSS  (OUT_IDX + N_TOKENS)
#define OUT_CB    (OUT_LOSS + 1)
#define OUT_CS    (OUT_CB + NUM_CODES * CODE_DIM)
#define OUT_EMA   (OUT_CS + NUM_CODES)

// smem layout (bytes)
#define SM_ZS     0                   // 64 d-rows x 256 tokens x 4B = 65536
#define SM_C0     65536               // code tile buf0: 64 x 272 = 17408
#define SM_C1     82944               // code tile buf1: 17408
#define SM_CNS    100352              // 1024 floats = 4096
#define SM_SIDX   104448              // 256 int = 1024
#define SM_SBEST  105472              // 256 float = 1024
#define SMEM_BYTES 106496

// ---------------- device scratch ----------------
__device__ __align__(16) u64 g_cbp[16 * 64 * 32];  // dense [chunk][dim][pair] code pairs
__device__ float g_dw[NUM_CODES * CODE_DIM];
__device__ float g_counts[NUM_CODES];
__device__ float g_cnorm[NUM_CODES];
__device__ float g_inv[NUM_CODES];
__device__ float g_loss;

// ---------------- helpers ----------------
__device__ __forceinline__ uint32_t smem_u32(const void* p) {
    uint32_t a;
    asm("{ .reg .u64 t; cvta.to.shared.u64 t, %1; cvt.u32.u64 %0, t; }" : "=r"(a) : "l"(p));
    return a;
}
__device__ __forceinline__ u64 pk2(float x, float y) {
    u64 r; asm("mov.b64 %0, {%1, %2};" : "=l"(r) : "f"(x), "f"(y)); return r;
}
__device__ __forceinline__ void upk2(u64 v, float& x, float& y) {
    asm("mov.b64 {%0, %1}, %2;" : "=f"(x), "=f"(y) : "l"(v));
}
__device__ __forceinline__ u64 fma2(u64 a, u64 b, u64 c) {
    u64 r; asm("fma.rn.f32x2 %0, %1, %2, %3;" : "=l"(r) : "l"(a), "l"(b), "l"(c)); return r;
}
__device__ __forceinline__ void cpa16(uint32_t dst, const void* src) {
    asm volatile("cp.async.cg.shared.global [%0], [%1], 16;" :: "r"(dst), "l"(src));
}
#define CP_COMMIT() asm volatile("cp.async.commit_group;" ::: "memory")
#define CP_WAIT1()  asm volatile("cp.async.wait_group 1;" ::: "memory")
#define CP_WAIT0()  asm volatile("cp.async.wait_group 0;" ::: "memory")

// ---------------- prep kernels (assign at launch position 3 for ncu) ----------------
__global__ void prep_zero_a_kernel() {
    int i = blockIdx.x * 256 + threadIdx.x;   // 8192 -> lower half of g_dw
    ((float4*)g_dw)[i] = make_float4(0.f, 0.f, 0.f, 0.f);
    if (i < NUM_CODES) g_counts[i] = 0.0f;
}

// dense: g_cbp[c*2048 + d*32 + p] = (cb[c*64+2p][d], cb[c*64+2p+1][d])
__global__ void prep_cb_kernel(const float* __restrict__ cb) {
    int i = blockIdx.x * 256 + threadIdx.x;   // 32768 threads
    int c = i >> 11, r = i & 2047;
    int d = r >> 5, p = r & 31;
    int k0 = c * 64 + 2 * p;
    g_cbp[i] = pk2(cb[(size_t)k0 * 64 + d], cb[(size_t)(k0 + 1) * 64 + d]);
    if (i < NUM_CODES) {
        float s = 0.0f;
        const float4* cr = (const float4*)(cb + (size_t)i * 64);
#pragma unroll
        for (int j = 0; j < 16; j++) {
            float4 w = cr[j];
            s += w.x * w.x + w.y * w.y + w.z * w.z + w.w * w.w;
        }
        g_cnorm[i] = s;
    }
}

__global__ void prep_zero_b_kernel() {
    int i = blockIdx.x * 256 + threadIdx.x;   // 8192 -> upper half of g_dw
    ((float4*)g_dw)[8192 + i] = make_float4(0.f, 0.f, 0.f, 0.f);
    if (i == 0) g_loss = 0.0f;
}

// ---------------- assign: f32x2 GEMM, 8 tokens x 8 codes per thread ----------------
// 256 threads, 256 tokens/CTA, 512 CTAs, 2 CTAs/SM (16 warps).
// cg = tid&7 (codes cg*8..cg*8+7 of the chunk), tgrp = tid>>3 (tokens tgrp*8..+7).
// z: scalar LDS.32 broadcasts + register dup; codes: packed pairs via 2 LDS.128.
__global__ void __launch_bounds__(256, 2)
assign_kernel(const float4* __restrict__ z4, const float4* __restrict__ cb4,
              float* __restrict__ out) {
    extern __shared__ __align__(16) char smem[];
    float* cns   = (float*)(smem + SM_CNS);
    int*   sidx  = (int*)(smem + SM_SIDX);
    float* sbest = (float*)(smem + SM_SBEST);

    const int tid  = threadIdx.x;
    const int cg   = tid & 7;
    const int tgrp = tid >> 3;           // 0..31, owns tokens tgrp*8..tgrp*8+7
    const int base = blockIdx.x * 256;
    const uint32_t sbase = smem_u32(smem);

    // ---- stage z: thread owns token tid; zs[d][t] plain f32 (1024B rows)
    {
        const float4* zsrc = z4 + (size_t)(base + tid) * 16;
#pragma unroll
        for (int j = 0; j < 16; j++) {
            float4 v = zsrc[j];
            *(float*)(smem + SM_ZS + (4 * j + 0) * 1024 + tid * 4) = v.x;
            *(float*)(smem + SM_ZS + (4 * j + 1) * 1024 + tid * 4) = v.y;
            *(float*)(smem + SM_ZS + (4 * j + 2) * 1024 + tid * 4) = v.z;
            *(float*)(smem + SM_ZS + (4 * j + 3) * 1024 + tid * 4) = v.w;
        }
    }
    // ---- resident code norms
#pragma unroll
    for (int i = 0; i < 4; i++) cns[tid + i * 256] = g_cnorm[tid + i * 256];

    // ---- cp.async prologue: chunk 0 -> buf0 (1024 x 16B, dense -> gapped rows)
    {
        const char* src = (const char*)g_cbp;
#pragma unroll
        for (int i = 0; i < 4; i++) {
            int l = tid + i * 256;
            int d = l >> 4, p = (l & 15) * 2;
            cpa16(sbase + SM_C0 + d * 272 + p * 8 + ((p >> 4) << 4), src + (size_t)l * 16);
        }
        CP_COMMIT();
    }

    float best[8];
    int   bidx[8];
#pragma unroll
    for (int t = 0; t < 8; t++) { best[t] = 3.0e38f; bidx[t] = 0; }
    const u64 NEG2 = pk2(-2.0f, -2.0f);

    for (int c = 0; c < 16; c++) {
        __syncthreads();   // prior compute done with the buffer being refilled
        if (c < 15) {
            const char* src = (const char*)(g_cbp + (size_t)(c + 1) * 2048);
            uint32_t boff = ((c + 1) & 1) ? SM_C1 : SM_C0;
#pragma unroll
            for (int i = 0; i < 4; i++) {
                int l = tid + i * 256;
                int d = l >> 4, p = (l & 15) * 2;
                cpa16(sbase + boff + d * 272 + p * 8 + ((p >> 4) << 4), src + (size_t)l * 16);
            }
            CP_COMMIT();
            CP_WAIT1();    // chunk c complete
        } else {
            CP_WAIT0();
        }
        __syncthreads();   // chunk c visible

        const char* cbuf = smem + ((c & 1) ? SM_C1 : SM_C0);

        u64 acc[32];
#pragma unroll
        for (int i = 0; i < 32; i++) acc[i] = 0ull;

#pragma unroll 8
        for (int d = 0; d < 64; d++) {
            const char* zrow = smem + SM_ZS + d * 1024 + tgrp * 32;
            const char* cr   = cbuf + d * 272 + cg * 32 + ((cg & 4) << 2);
            ulonglong2 ca  = *(const ulonglong2*)cr;         // code pairs 0,1
            ulonglong2 cb2 = *(const ulonglong2*)(cr + 16);  // code pairs 2,3
            u64 cc0 = ca.x, cc1 = ca.y, cc2 = cb2.x, cc3 = cb2.y;
            // half-step A: tokens 0..3 (short dup lifetimes for register pressure)
#pragma unroll
            for (int t = 0; t < 4; t++) {
                float zv = *(const float*)(zrow + t * 4);
                u64 zz = pk2(zv, zv);
                acc[t * 4 + 0] = fma2(zz, cc0, acc[t * 4 + 0]);
                acc[t * 4 + 1] = fma2(zz, cc1, acc[t * 4 + 1]);
                acc[t * 4 + 2] = fma2(zz, cc2, acc[t * 4 + 2]);
                acc[t * 4 + 3] = fma2(zz, cc3, acc[t * 4 + 3]);
            }
            // half-step B: tokens 4..7
#pragma unroll
            for (int t = 4; t < 8; t++) {
                float zv = *(const float*)(zrow + t * 4);
                u64 zz = pk2(zv, zv);
                acc[t * 4 + 0] = fma2(zz, cc0, acc[t * 4 + 0]);
                acc[t * 4 + 1] = fma2(zz, cc1, acc[t * 4 + 1]);
                acc[t * 4 + 2] = fma2(zz, cc2, acc[t * 4 + 2]);
                acc[t * 4 + 3] = fma2(zz, cc3, acc[t * 4 + 3]);
            }
        }

        // ---- epilogue: score pair = cn - 2*dot, running argmin
        const int kb = c * 64;
#pragma unroll
        for (int q = 0; q < 4; q++) {
            u64 cnp = *(const u64*)&cns[kb + cg * 8 + 2 * q];
            int idx0 = kb + cg * 8 + 2 * q;
#pragma unroll
            for (int t = 0; t < 8; t++) {
                u64 sp = fma2(acc[t * 4 + q], NEG2, cnp);
                float s0, s1;
                upk2(sp, s0, s1);
                if (s0 < best[t]) { best[t] = s0; bidx[t] = idx0; }
                if (s1 < best[t]) { best[t] = s1; bidx[t] = idx0 + 1; }
            }
        }
    }

    // ---- cross-lane argmin over 8 cg lanes (lane bits 0..2), tie-break lowest index
#pragma unroll
    for (int t = 0; t < 8; t++) {
        float v = best[t];
        int   i = bidx[t];
#pragma unroll
        for (int off = 1; off <= 4; off <<= 1) {
            float ov = __shfl_xor_sync(0xffffffffu, v, off);
            int   oi = __shfl_xor_sync(0xffffffffu, i, off);
            if (ov < v || (ov == v && oi < i)) { v = ov; i = oi; }
        }
        if (cg == 0) { sidx[tgrp * 8 + t] = i; sbest[tgrp * 8 + t] = v; }
    }
    __syncthreads();

    // ---- scatter: thread owns token tid (z from smem, conflict-free)
    {
        int idx = sidx[tid];
        int tok = base + tid;
        out[OUT_IDX + tok] = (float)idx;
        atomicAdd(&g_counts[idx], 1.0f);
        float zn = 0.0f;
        float* dwp = &g_dw[idx * 64];
#pragma unroll 8
        for (int d = 0; d < 64; d++) {
            float zv = *(const float*)(smem + SM_ZS + d * 1024 + tid * 4);
            zn += zv * zv;
            atomicAdd(&dwp[d], zv);
        }
        float lp = zn + sbest[tid];   // exact d2min
#pragma unroll
        for (int off = 16; off > 0; off >>= 1)
            lp += __shfl_down_sync(0xffffffffu, lp, off);
        if ((tid & 31) == 0) atomicAdd(&g_loss, lp);
    }

    // ---- quantized: cooperative coalesced gather
    float4* outq = (float4*)out;   // OUT_Q == 0
#pragma unroll
    for (int i = 0; i < 16; i++) {
        int l = tid + i * 256;
        int t = l >> 4, j = l & 15;
        outq[(size_t)(base + t) * 16 + j] = cb4[(size_t)sidx[t] * 16 + j];
    }
}

// ---------------- finalize A: per-code stats + loss ----------------
__global__ void finalize_a_kernel(const float* __restrict__ cs_in,
                                  float* __restrict__ out) {
    __shared__ float s[1024];
    int k = threadIdx.x;
    float ncs = DECAY * cs_in[k] + OMD * g_counts[k];
    s[k] = ncs;
    __syncthreads();
    for (int st = 512; st > 0; st >>= 1) {
        if (k < st) s[k] += s[k + st];
        __syncthreads();
    }
    float n   = s[0];
    float csk = (ncs + EPS) / (n + NUM_CODES * EPS) * n;
    out[OUT_CS + k] = ncs;
    g_inv[k] = 1.0f / csk;
    if (k == 0) out[OUT_LOSS] = g_loss * (1.0f / (float)(N_TOKENS * CODE_DIM));
}

// ---------------- finalize B: parallel EMA + codebook update ----------------
__global__ void finalize_b_kernel(const float* __restrict__ ema_in,
                                  float* __restrict__ out) {
    int i = blockIdx.x * 256 + threadIdx.x;   // 65536 threads
    float e = DECAY * ema_in[i] + OMD * g_dw[i];
    out[OUT_EMA + i] = e;
    out[OUT_CB + i]  = e * g_inv[i >> 6];
}

extern "C" void kernel_launch(void* const* d_in, const int* in_sizes, int n_in,
                              void* d_out, int out_size) {
    const float* z   = (const float*)d_in[0];
    const float* cb  = (const float*)d_in[1];
    const float* cs  = (const float*)d_in[2];
    const float* ema = (const float*)d_in[3];
    float* out = (float*)d_out;

    static int smem_set = 0;
    if (!smem_set) {
        cudaFuncSetAttribute(assign_kernel,
                             cudaFuncAttributeMaxDynamicSharedMemorySize, SMEM_BYTES);
        smem_set = 1;
    }

    prep_zero_a_kernel<<<32, 256>>>();                                   // pos 0
    prep_cb_kernel<<<128, 256>>>(cb);                                    // pos 1
    prep_zero_b_kernel<<<32, 256>>>();                                   // pos 2
    assign_kernel<<<512, 256, SMEM_BYTES>>>((const float4*)z,            // pos 3
                                            (const float4*)cb, out);
    finalize_a_kernel<<<1, 1024>>>(cs, out);                             // pos 4
    finalize_b_kernel<<<256, 256>>>(ema, out);                           // pos 5
}

// round 15
// speedup vs baseline: 1.2395x; 1.1804x over previous
#include <cuda_runtime.h>
#include <cstdint>

typedef unsigned long long u64;

#define N_TOKENS  131072
#define NUM_CODES 1024
#define CODE_DIM  64
#define DECAY     0.99f
#define OMD       0.01f
#define EPS       1e-5f

#define OUT_Q     0
#define OUT_IDX   (N_TOKENS * CODE_DIM)
#define OUT_LOSS  (OUT_IDX + N_TOKENS)
#define OUT_CB    (OUT_LOSS + 1)
#define OUT_CS    (OUT_CB + NUM_CODES * CODE_DIM)
#define OUT_EMA   (OUT_CS + NUM_CODES)

// smem layout (bytes)  — R10 champion layout
#define SM_ZS     0                 // 64 d-rows x 128 tokens x 4B = 32768 (plain f32)
#define SM_C0     32768             // code tile buf0: 64 x 272 = 17408
#define SM_C1     50176             // code tile buf1: 17408
#define SM_CNS    67584             // 1024 floats = 4096
#define SM_SIDX   71680             // 128 int
#define SM_SBEST  72192             // 128 float
#define SMEM_BYTES 72704

// ---------------- device scratch ----------------
__device__ __align__(16) u64 g_cbp[16 * 64 * 32];  // [chunk][dim][pair] packed code pairs
__device__ float g_dw[NUM_CODES * CODE_DIM];
__device__ float g_counts[NUM_CODES];
__device__ float g_cnorm[NUM_CODES];
__device__ float g_inv[NUM_CODES];
__device__ float g_loss;

// ---------------- helpers ----------------
__device__ __forceinline__ uint32_t smem_u32(const void* p) {
    uint32_t a;
    asm("{ .reg .u64 t; cvta.to.shared.u64 t, %1; cvt.u32.u64 %0, t; }" : "=r"(a) : "l"(p));
    return a;
}
__device__ __forceinline__ u64 pk2(float x, float y) {
    u64 r; asm("mov.b64 %0, {%1, %2};" : "=l"(r) : "f"(x), "f"(y)); return r;
}
__device__ __forceinline__ void upk2(u64 v, float& x, float& y) {
    asm("mov.b64 {%0, %1}, %2;" : "=f"(x), "=f"(y) : "l"(v));
}
__device__ __forceinline__ u64 fma2(u64 a, u64 b, u64 c) {
    u64 r; asm("fma.rn.f32x2 %0, %1, %2, %3;" : "=l"(r) : "l"(a), "l"(b), "l"(c)); return r;
}
__device__ __forceinline__ void cpa16(uint32_t dst, const void* src) {
    asm volatile("cp.async.cg.shared.global [%0], [%1], 16;" :: "r"(dst), "l"(src));
}
#define CP_COMMIT() asm volatile("cp.async.commit_group;" ::: "memory")
#define CP_WAIT1()  asm volatile("cp.async.wait_group 1;" ::: "memory")
#define CP_WAIT0()  asm volatile("cp.async.wait_group 0;" ::: "memory")

// ---------------- prep kernels (assign at launch position 3 for ncu) ----------------
__global__ void prep_zero_a_kernel() {
    int i = blockIdx.x * 256 + threadIdx.x;   // 8192 -> lower half of g_dw
    ((float4*)g_dw)[i] = make_float4(0.f, 0.f, 0.f, 0.f);
    if (i < NUM_CODES) g_counts[i] = 0.0f;
}

__global__ void prep_cb_kernel(const float* __restrict__ cb) {
    int i = blockIdx.x * 256 + threadIdx.x;   // 32768 threads
    int c = i >> 11, r = i & 2047;
    int d = r >> 5, p = r & 31;
    int k0 = c * 64 + 2 * p;
    g_cbp[i] = pk2(cb[(size_t)k0 * 64 + d], cb[(size_t)(k0 + 1) * 64 + d]);
    if (i < NUM_CODES) {
        float s = 0.0f;
        const float4* cr = (const float4*)(cb + (size_t)i * 64);
#pragma unroll
        for (int j = 0; j < 16; j++) {
            float4 w = cr[j];
            s += w.x * w.x + w.y * w.y + w.z * w.z + w.w * w.w;
        }
        g_cnorm[i] = s;
    }
}

__global__ void prep_zero_b_kernel() {
    int i = blockIdx.x * 256 + threadIdx.x;   // 8192 -> upper half of g_dw
    ((float4*)g_dw)[8192 + i] = make_float4(0.f, 0.f, 0.f, 0.f);
    if (i == 0) g_loss = 0.0f;
}

// ---------------- assign: f32x2 GEMM, 8 tok x 8 codes, reg-double-buffered ----------------
// 128 threads, 128 tokens/CTA, 1024 CTAs, 3 CTAs/SM.
// cg = tid&7 (8 codes), tgrp = tid>>3 (8 tokens).
__global__ void __launch_bounds__(128, 3)
assign_kernel(const float4* __restrict__ z4, const float4* __restrict__ cb4,
              float* __restrict__ out) {
    extern __shared__ __align__(16) char smem[];
    float* cns   = (float*)(smem + SM_CNS);
    int*   sidx  = (int*)(smem + SM_SIDX);
    float* sbest = (float*)(smem + SM_SBEST);

    const int tid  = threadIdx.x;
    const int cg   = tid & 7;
    const int tgrp = tid >> 3;           // 0..15, owns tokens tgrp*8..tgrp*8+7
    const int base = blockIdx.x * 128;
    const uint32_t sbase = smem_u32(smem);

    // ---- stage z: thread owns token tid; zs[d][t] plain f32 (512B rows)
    {
        const float4* zsrc = z4 + (size_t)(base + tid) * 16;
#pragma unroll
        for (int j = 0; j < 16; j++) {
            float4 v = zsrc[j];
            *(float*)(smem + SM_ZS + (4 * j + 0) * 512 + tid * 4) = v.x;
            *(float*)(smem + SM_ZS + (4 * j + 1) * 512 + tid * 4) = v.y;
            *(float*)(smem + SM_ZS + (4 * j + 2) * 512 + tid * 4) = v.z;
            *(float*)(smem + SM_ZS + (4 * j + 3) * 512 + tid * 4) = v.w;
        }
    }
    // ---- resident code norms
#pragma unroll
    for (int i = 0; i < 8; i++) cns[tid + i * 128] = g_cnorm[tid + i * 128];

    // ---- cp.async prologue: chunk 0 -> buf0
    {
        const char* src = (const char*)g_cbp;
#pragma unroll
        for (int i = 0; i < 8; i++) {
            int l = tid + i * 128;
            int d = l >> 4, p = (l & 15) * 2;
            cpa16(sbase + SM_C0 + d * 272 + p * 8 + ((p >> 4) << 4), src + (size_t)l * 16);
        }
        CP_COMMIT();
    }

    float best[8];
    int   bidx[8];
#pragma unroll
    for (int t = 0; t < 8; t++) { best[t] = 3.0e38f; bidx[t] = 0; }
    const u64 NEG2 = pk2(-2.0f, -2.0f);

    for (int c = 0; c < 16; c++) {
        __syncthreads();   // prior compute done with the buffer being refilled
        if (c < 15) {
            const char* src = (const char*)(g_cbp + (size_t)(c + 1) * 2048);
            uint32_t boff = ((c + 1) & 1) ? SM_C1 : SM_C0;
#pragma unroll
            for (int i = 0; i < 8; i++) {
                int l = tid + i * 128;
                int d = l >> 4, p = (l & 15) * 2;
                cpa16(sbase + boff + d * 272 + p * 8 + ((p >> 4) << 4), src + (size_t)l * 16);
            }
            CP_COMMIT();
            CP_WAIT1();    // chunk c complete
        } else {
            CP_WAIT0();
        }
        __syncthreads();   // chunk c visible

        const char* cbuf = smem + ((c & 1) ? SM_C1 : SM_C0);
        const char* crb  = cbuf + cg * 32 + ((cg & 4) << 2);
        const char* zrb  = smem + SM_ZS + tgrp * 32;

        u64 acc[32];
#pragma unroll
        for (int i = 0; i < 32; i++) acc[i] = 0ull;

        // ---- preload dim 0 operands
        ulonglong2 ca  = *(const ulonglong2*)crb;
        ulonglong2 cb2 = *(const ulonglong2*)(crb + 16);
        float zf0 = *(const float*)(zrb + 0);
        float zf1 = *(const float*)(zrb + 4);
        float zf2 = *(const float*)(zrb + 8);
        float zf3 = *(const float*)(zrb + 12);
        float zf4 = *(const float*)(zrb + 16);
        float zf5 = *(const float*)(zrb + 20);
        float zf6 = *(const float*)(zrb + 24);
        float zf7 = *(const float*)(zrb + 28);

#pragma unroll 8
        for (int d = 0; d < 64; d++) {
            // current operands
            u64 cc0 = ca.x, cc1 = ca.y, cc2 = cb2.x, cc3 = cb2.y;
            u64 zz0 = pk2(zf0, zf0), zz1 = pk2(zf1, zf1);
            u64 zz2 = pk2(zf2, zf2), zz3 = pk2(zf3, zf3);
            u64 zz4 = pk2(zf4, zf4), zz5 = pk2(zf5, zf5);
            u64 zz6 = pk2(zf6, zf6), zz7 = pk2(zf7, zf7);
            // prefetch dim d+1 (loads retire while fmas below execute)
            if (d < 63) {
                const char* crn = crb + (d + 1) * 272;
                const char* zrn = zrb + (d + 1) * 512;
                ca  = *(const ulonglong2*)crn;
                cb2 = *(const ulonglong2*)(crn + 16);
                zf0 = *(const float*)(zrn + 0);
                zf1 = *(const float*)(zrn + 4);
                zf2 = *(const float*)(zrn + 8);
                zf3 = *(const float*)(zrn + 12);
                zf4 = *(const float*)(zrn + 16);
                zf5 = *(const float*)(zrn + 20);
                zf6 = *(const float*)(zrn + 24);
                zf7 = *(const float*)(zrn + 28);
            }
            acc[0]  = fma2(zz0, cc0, acc[0]);
            acc[1]  = fma2(zz0, cc1, acc[1]);
            acc[2]  = fma2(zz0, cc2, acc[2]);
            acc[3]  = fma2(zz0, cc3, acc[3]);
            acc[4]  = fma2(zz1, cc0, acc[4]);
            acc[5]  = fma2(zz1, cc1, acc[5]);
            acc[6]  = fma2(zz1, cc2, acc[6]);
            acc[7]  = fma2(zz1, cc3, acc[7]);
            acc[8]  = fma2(zz2, cc0, acc[8]);
            acc[9]  = fma2(zz2, cc1, acc[9]);
            acc[10] = fma2(zz2, cc2, acc[10]);
            acc[11] = fma2(zz2, cc3, acc[11]);
            acc[12] = fma2(zz3, cc0, acc[12]);
            acc[13] = fma2(zz3, cc1, acc[13]);
            acc[14] = fma2(zz3, cc2, acc[14]);
            acc[15] = fma2(zz3, cc3, acc[15]);
            acc[16] = fma2(zz4, cc0, acc[16]);
            acc[17] = fma2(zz4, cc1, acc[17]);
            acc[18] = fma2(zz4, cc2, acc[18]);
            acc[19] = fma2(zz4, cc3, acc[19]);
            acc[20] = fma2(zz5, cc0, acc[20]);
            acc[21] = fma2(zz5, cc1, acc[21]);
            acc[22] = fma2(zz5, cc2, acc[22]);
            acc[23] = fma2(zz5, cc3, acc[23]);
            acc[24] = fma2(zz6, cc0, acc[24]);
            acc[25] = fma2(zz6, cc1, acc[25]);
            acc[26] = fma2(zz6, cc2, acc[26]);
            acc[27] = fma2(zz6, cc3, acc[27]);
            acc[28] = fma2(zz7, cc0, acc[28]);
            acc[29] = fma2(zz7, cc1, acc[29]);
            acc[30] = fma2(zz7, cc2, acc[30]);
            acc[31] = fma2(zz7, cc3, acc[31]);
        }

        // ---- epilogue: score pair = cn - 2*dot, running argmin
        const int kb = c * 64;
#pragma unroll
        for (int q = 0; q < 4; q++) {
            u64 cnp = *(const u64*)&cns[kb + cg * 8 + 2 * q];
            int idx0 = kb + cg * 8 + 2 * q;
#pragma unroll
            for (int t = 0; t < 8; t++) {
                u64 sp = fma2(acc[t * 4 + q], NEG2, cnp);
                float s0, s1;
                upk2(sp, s0, s1);
                if (s0 < best[t]) { best[t] = s0; bidx[t] = idx0; }
                if (s1 < best[t]) { best[t] = s1; bidx[t] = idx0 + 1; }
            }
        }
    }

    // ---- cross-lane argmin over 8 cg lanes (lane bits 0..2), tie-break lowest index
#pragma unroll
    for (int t = 0; t < 8; t++) {
        float v = best[t];
        int   i = bidx[t];
#pragma unroll
        for (int off = 1; off <= 4; off <<= 1) {
            float ov = __shfl_xor_sync(0xffffffffu, v, off);
            int   oi = __shfl_xor_sync(0xffffffffu, i, off);
            if (ov < v || (ov == v && oi < i)) { v = ov; i = oi; }
        }
        if (cg == 0) { sidx[tgrp * 8 + t] = i; sbest[tgrp * 8 + t] = v; }
    }
    __syncthreads();

    // ---- scatter: thread owns token tid (z from smem, conflict-free)
    {
        int idx = sidx[tid];
        int tok = base + tid;
        out[OUT_IDX + tok] = (float)idx;
        atomicAdd(&g_counts[idx], 1.0f);
        float zn = 0.0f;
        float* dwp = &g_dw[idx * 64];
#pragma unroll 8
        for (int d = 0; d < 64; d++) {
            float zv = *(const float*)(smem + SM_ZS + d * 512 + tid * 4);
            zn += zv * zv;
            atomicAdd(&dwp[d], zv);
        }
        float lp = zn + sbest[tid];   // exact d2min
#pragma unroll
        for (int off = 16; off > 0; off >>= 1)
            lp += __shfl_down_sync(0xffffffffu, lp, off);
        if ((tid & 31) == 0) atomicAdd(&g_loss, lp);
    }

    // ---- quantized: cooperative coalesced gather
    float4* outq = (float4*)out;   // OUT_Q == 0
#pragma unroll
    for (int i = 0; i < 16; i++) {
        int l = tid + i * 128;
        int t = l >> 4, j = l & 15;
        outq[(size_t)(base + t) * 16 + j] = cb4[(size_t)sidx[t] * 16 + j];
    }
}

// ---------------- finalize A: per-code stats + loss ----------------
__global__ void finalize_a_kernel(const float* __restrict__ cs_in,
                                  float* __restrict__ out) {
    __shared__ float s[1024];
    int k = threadIdx.x;
    float ncs = DECAY * cs_in[k] + OMD * g_counts[k];
    s[k] = ncs;
    __syncthreads();
    for (int st = 512; st > 0; st >>= 1) {
        if (k < st) s[k] += s[k + st];
        __syncthreads();
    }
    float n   = s[0];
    float csk = (ncs + EPS) / (n + NUM_CODES * EPS) * n;
    out[OUT_CS + k] = ncs;
    g_inv[k] = 1.0f / csk;
    if (k == 0) out[OUT_LOSS] = g_loss * (1.0f / (float)(N_TOKENS * CODE_DIM));
}

// ---------------- finalize B: parallel EMA + codebook update ----------------
__global__ void finalize_b_kernel(const float* __restrict__ ema_in,
                                  float* __restrict__ out) {
    int i = blockIdx.x * 256 + threadIdx.x;   // 65536 threads
    float e = DECAY * ema_in[i] + OMD * g_dw[i];
    out[OUT_EMA + i] = e;
    out[OUT_CB + i]  = e * g_inv[i >> 6];
}

extern "C" void kernel_launch(void* const* d_in, const int* in_sizes, int n_in,
                              void* d_out, int out_size) {
    const float* z   = (const float*)d_in[0];
    const float* cb  = (const float*)d_in[1];
    const float* cs  = (const float*)d_in[2];
    const float* ema = (const float*)d_in[3];
    float* out = (float*)d_out;

    static int smem_set = 0;
    if (!smem_set) {
        cudaFuncSetAttribute(assign_kernel,
                             cudaFuncAttributeMaxDynamicSharedMemorySize, SMEM_BYTES);
        smem_set = 1;
    }

    prep_zero_a_kernel<<<32, 256>>>();                                   // pos 0
    prep_cb_kernel<<<128, 256>>>(cb);                                    // pos 1
    prep_zero_b_kernel<<<32, 256>>>();                                   // pos 2
    assign_kernel<<<1024, 128, SMEM_BYTES>>>((const float4*)z,           // pos 3
                                             (const float4*)cb, out);
    finalize_a_kernel<<<1, 1024>>>(cs, out);                             // pos 4
    finalize_b_kernel<<<256, 256>>>(ema, out);                           // pos 5
}